// round 14
// baseline (speedup 1.0000x reference)
#include <cuda_runtime.h>
#include <cuda_bf16.h>
#include <cuda_fp16.h>
#include <cstdint>
#include <math.h>

#define HT   128
#define CC   256
#define FF   128
#define BB   4
#define NU   32
#define NOUT 2304
#define NG   1024
#define PIF  3.14159265358979323846f

typedef __nv_bfloat16 bf16;

// ---------------- scratch globals ----------------
__device__ __align__(16) bf16   g_Wgh[4 * NG * 32];
__device__ __align__(16) bf16   g_Wgl[4 * NG * 32];
__device__ __align__(16) float  g_bg[4 * NG];
__device__ __align__(16) float  g_Hc[128 * 32];
__device__ __align__(16) float  g_Wc[128 * 32];
__device__ __align__(16) float  g_Cc[32];
__device__ __align__(16) bf16   g_x4h[(size_t)16384 * 32];
__device__ __align__(16) bf16   g_x4l[(size_t)16384 * 32];
__device__ __align__(16) __half g_WpT16[(size_t)FF * CC];     // [n][k] fp16
__device__ __align__(16) __half g_ker16[(size_t)16384 * NG];  // fp16 grouped kernels
__device__ __align__(16) __half g_x16[(size_t)BB * 64 * 64 * CC]; // fp16 main_in (8.4MB)

__device__ __forceinline__ void split_bf(float v, bf16& hi, bf16& lo) {
    hi = __float2bfloat16(v);
    lo = __float2bfloat16(v - __bfloat162float(hi));
}
__device__ __forceinline__ void mma16816(float c[4], const uint32_t a[4], const uint32_t b[2]) {
    asm volatile(
        "mma.sync.aligned.m16n8k16.row.col.f32.bf16.bf16.f32 "
        "{%0,%1,%2,%3}, {%4,%5,%6,%7}, {%8,%9}, {%0,%1,%2,%3};"
        : "+f"(c[0]), "+f"(c[1]), "+f"(c[2]), "+f"(c[3])
        : "r"(a[0]), "r"(a[1]), "r"(a[2]), "r"(a[3]), "r"(b[0]), "r"(b[1]));
}
__device__ __forceinline__ void mma16816h(float c[4], const uint32_t a[4], const uint32_t b[2]) {
    asm volatile(
        "mma.sync.aligned.m16n8k16.row.col.f32.f16.f16.f32 "
        "{%0,%1,%2,%3}, {%4,%5,%6,%7}, {%8,%9}, {%0,%1,%2,%3};"
        : "+f"(c[0]), "+f"(c[1]), "+f"(c[2]), "+f"(c[3])
        : "r"(a[0]), "r"(a[1]), "r"(a[2]), "r"(a[3]), "r"(b[0]), "r"(b[1]));
}
__device__ __forceinline__ void ldsm_x4(uint32_t& r0, uint32_t& r1, uint32_t& r2, uint32_t& r3,
                                        uint32_t addr) {
    asm volatile("ldmatrix.sync.aligned.m8n8.x4.shared.b16 {%0,%1,%2,%3}, [%4];"
                 : "=r"(r0), "=r"(r1), "=r"(r2), "=r"(r3) : "r"(addr));
}
__device__ __forceinline__ int grp(int t, int par) { return (t == 0) ? 0 : (t == 2) ? 1 : (par ? 0 : 1); }

__device__ __forceinline__ void cp16(uint32_t dst, const void* src, int sz) {
    asm volatile("cp.async.cg.shared.global [%0], [%1], 16, %2;"
                 :: "r"(dst), "l"(src), "r"(sz));
}
#define CP_COMMIT() asm volatile("cp.async.commit_group;" ::: "memory")
#define CP_WAIT0()  asm volatile("cp.async.wait_group 0;" ::: "memory")

// ---------------------------------------------------------------------------
// x2h: main_in fp32 -> fp16
// ---------------------------------------------------------------------------
__global__ __launch_bounds__(256) void x2h_kernel(const float* __restrict__ main_in)
{
    size_t i = ((size_t)blockIdx.x * 256 + threadIdx.x) * 4;
    float4 v = *(const float4*)&main_in[i];
    __half2 p0 = __floats2half2_rn(v.x, v.y);
    __half2 p1 = __floats2half2_rn(v.z, v.w);
    *(__half2*)&g_x16[i]     = p0;
    *(__half2*)&g_x16[i + 2] = p1;
}

// ---------------------------------------------------------------------------
// prep
// ---------------------------------------------------------------------------
__global__ __launch_bounds__(256) void prep_kernel(
    const float* __restrict__ Wo, const float* __restrict__ bo,
    const float* __restrict__ Wp,
    const float* __restrict__ W1, const float* __restrict__ b1)
{
    int idx = blockIdx.x * 256 + threadIdx.x;
    if (idx < 4 * NG * 32) {
        int par = idx >> 15, rem = idx & 32767;
        int n = rem >> 5, k = rem & 31;
        int g = n >> 8, c = n & 255, gr = g >> 1, gc = g & 1;
        int ph = par >> 1, pw = par & 1;
        float s = 0.0f;
        #pragma unroll
        for (int tr = 0; tr < 3; ++tr)
            #pragma unroll
            for (int tc = 0; tc < 3; ++tc)
                if (grp(tr, ph) == gr && grp(tc, pw) == gc)
                    s += Wo[(size_t)k * NOUT + (tr * 3 + tc) * 256 + c];
        bf16 hi, lo; split_bf(s, hi, lo);
        g_Wgh[idx] = hi; g_Wgl[idx] = lo;
    } else if ((idx -= 4 * NG * 32) < 4 * NG) {
        int par = idx >> 10, n = idx & 1023;
        int g = n >> 8, c = n & 255, gr = g >> 1, gc = g & 1;
        int ph = par >> 1, pw = par & 1;
        float s = 0.0f;
        #pragma unroll
        for (int tr = 0; tr < 3; ++tr)
            #pragma unroll
            for (int tc = 0; tc < 3; ++tc)
                if (grp(tr, ph) == gr && grp(tc, pw) == gc)
                    s += bo[(tr * 3 + tc) * 256 + c];
        g_bg[idx] = s;
    } else if ((idx -= 4 * NG) < FF * CC) {
        int n = idx >> 8, k = idx & 255;
        g_WpT16[idx] = __float2half(Wp[(size_t)k * FF + n]);
    } else if ((idx -= FF * CC) < 4096) {
        int h = idx >> 5, j = idx & 31;
        float s = 0.0f;
        for (int i = 0; i < 25; ++i) {
            float f = 1.0f + (float)i * (1.0f / 24.0f);
            s += cosf(PIF * (2.0f * h * (1.0f / 127.0f) + 1.0f) * f) * W1[i * 32 + j];
        }
        g_Hc[idx] = s;
    } else if ((idx -= 4096) < 4096) {
        int w = idx >> 5, j = idx & 31;
        float s = 0.0f;
        for (int i = 0; i < 25; ++i) {
            float f = 1.0f + (float)i * (1.0f / 24.0f);
            s += cosf(PIF * (2.0f * w * (1.0f / 127.0f) + 1.0f) * f) * W1[(25 + i) * 32 + j];
        }
        g_Wc[idx] = s;
    } else if ((idx -= 4096) < 32) {
        int j = idx;
        float s = b1[j];
        for (int i = 0; i < 50; ++i) {
            float f = 1.0f + (float)(i % 25) * (1.0f / 24.0f);
            s += cosf(PIF * 5.0f * f) * W1[(50 + i) * 32 + j];
        }
        for (int i = 100; i < 118; ++i) s -= W1[i * 32 + j];
        g_Cc[j] = s;
    }
}

// ---------------------------------------------------------------------------
// mlp: 64 px/CTA (grid 256) -> x4 hi/lo, parity-major p'
// ---------------------------------------------------------------------------
__global__ __launch_bounds__(256) void mlp_kernel(
    const float* __restrict__ W2, const float* __restrict__ b2,
    const float* __restrict__ W3, const float* __restrict__ b3,
    const float* __restrict__ W4, const float* __restrict__ b4)
{
    __shared__ float xa[64][32];
    __shared__ float xb[64][32];
    const int tid = threadIdx.x;
    const int pix0 = blockIdx.x * 64;

    for (int o = tid; o < 2048; o += 256) {
        int p = o >> 5, j = o & 31;
        int pix = pix0 + p, h = pix >> 7, w = pix & 127;
        xa[p][j] = fmaxf(g_Hc[h * 32 + j] + g_Wc[w * 32 + j] + g_Cc[j], 0.0f);
    }
    __syncthreads();
    for (int o = tid; o < 2048; o += 256) {
        int p = o >> 5, j = o & 31;
        float s = b2[j];
        #pragma unroll
        for (int k = 0; k < NU; ++k) s += xa[p][k] * W2[k * NU + j];
        xb[p][j] = fmaxf(s, 0.0f);
    }
    __syncthreads();
    for (int o = tid; o < 2048; o += 256) {
        int p = o >> 5, j = o & 31;
        float s = b3[j];
        #pragma unroll
        for (int k = 0; k < NU; ++k) s += xb[p][k] * W3[k * NU + j];
        xa[p][j] = fmaxf(s, 0.0f);
    }
    __syncthreads();
    for (int o = tid; o < 2048; o += 256) {
        int p = o >> 5, j = o & 31;
        float s = b4[j];
        #pragma unroll
        for (int k = 0; k < NU; ++k) s += xa[p][k] * W4[k * NU + j];
        float v = fmaxf(s, 0.0f);
        int pix = pix0 + p, h = pix >> 7, w = pix & 127;
        int pp = (((h & 1) << 1) | (w & 1)) * 4096 + (h >> 1) * 64 + (w >> 1);
        bf16 hi, lo; split_bf(v, hi, lo);
        size_t o2 = (size_t)pp * 32 + j;
        g_x4h[o2] = hi; g_x4l[o2] = lo;
    }
}

// ---------------------------------------------------------------------------
// gemm1: g_ker16 = fp16(x4 @ Wg[par] + bg[par])
// ---------------------------------------------------------------------------
__global__ __launch_bounds__(256) void gemm1_kernel()
{
    __shared__ __align__(16) bf16 As[128 * 72];
    __shared__ __align__(16) bf16 Bs[128 * 72];

    const int tid = threadIdx.x;
    const int wid = tid >> 5, lane = tid & 31;
    const int gid = lane >> 2, tig = lane & 3;
    const int m0 = blockIdx.x * 128, n0g = blockIdx.y * 128;
    const int par = blockIdx.x >> 5;
    const int wm0 = (wid & 3) * 32, wn0 = (wid >> 2) * 64;

    const bf16* WgH = g_Wgh + (size_t)par * NG * 32;
    const bf16* WgL = g_Wgl + (size_t)par * NG * 32;

    for (int i = tid; i < 512; i += 256) {
        int r = i >> 2, q = (i & 3) * 8;
        *(uint4*)&As[r * 72 + q]      = *(const uint4*)&g_x4h[(size_t)(m0 + r) * 32 + q];
        *(uint4*)&As[r * 72 + 32 + q] = *(const uint4*)&g_x4l[(size_t)(m0 + r) * 32 + q];
        *(uint4*)&Bs[r * 72 + q]      = *(const uint4*)&WgH[(size_t)(n0g + r) * 32 + q];
        *(uint4*)&Bs[r * 72 + 32 + q] = *(const uint4*)&WgL[(size_t)(n0g + r) * 32 + q];
    }
    __syncthreads();

    const uint32_t smA = (uint32_t)__cvta_generic_to_shared(As);
    const uint32_t smB = (uint32_t)__cvta_generic_to_shared(Bs);
    const int aRow = (lane & 7) + ((lane >> 3) & 1) * 8;
    const int aCol = ((lane >> 4) & 1) * 8;
    const int bRow = (lane & 7) + ((lane >> 4) & 1) * 8;
    const int bCol = ((lane >> 3) & 1) * 8;

    float c[2][8][4];
    #pragma unroll
    for (int i = 0; i < 2; ++i)
        #pragma unroll
        for (int j = 0; j < 8; ++j)
            #pragma unroll
            for (int e = 0; e < 4; ++e) c[i][j][e] = 0.0f;

    #pragma unroll
    for (int ks = 0; ks < 2; ++ks) {
        const int kb = ks * 16;
        uint32_t aH[2][4], aL[2][4], bH[8][2], bL[8][2];
        #pragma unroll
        for (int mf = 0; mf < 2; ++mf) {
            uint32_t adr = smA + (uint32_t)((wm0 + mf * 16 + aRow) * 72 + kb + aCol) * 2;
            ldsm_x4(aH[mf][0], aH[mf][1], aH[mf][2], aH[mf][3], adr);
            ldsm_x4(aL[mf][0], aL[mf][1], aL[mf][2], aL[mf][3], adr + 64);
        }
        #pragma unroll
        for (int nf = 0; nf < 8; nf += 2) {
            uint32_t adr = smB + (uint32_t)((wn0 + nf * 8 + bRow) * 72 + kb + bCol) * 2;
            ldsm_x4(bH[nf][0], bH[nf][1], bH[nf + 1][0], bH[nf + 1][1], adr);
            ldsm_x4(bL[nf][0], bL[nf][1], bL[nf + 1][0], bL[nf + 1][1], adr + 64);
        }
        #pragma unroll
        for (int mf = 0; mf < 2; ++mf)
            #pragma unroll
            for (int nf = 0; nf < 8; ++nf) {
                mma16816(c[mf][nf], aH[mf], bH[nf]);
                mma16816(c[mf][nf], aH[mf], bL[nf]);
                mma16816(c[mf][nf], aL[mf], bH[nf]);
            }
    }

    const float* bgp = g_bg + par * NG;
    #pragma unroll
    for (int mf = 0; mf < 2; ++mf) {
        int gm = m0 + wm0 + mf * 16 + gid;
        #pragma unroll
        for (int nf = 0; nf < 8; ++nf) {
            int gn = n0g + wn0 + nf * 8 + tig * 2;
            float bx = __ldg(&bgp[gn]), by = __ldg(&bgp[gn + 1]);
            __half2 p0 = __floats2half2_rn(c[mf][nf][0] + bx, c[mf][nf][1] + by);
            __half2 p1 = __floats2half2_rn(c[mf][nf][2] + bx, c[mf][nf][3] + by);
            *(__half2*)&g_ker16[(size_t)gm * NG + gn]       = p0;
            *(__half2*)&g_ker16[(size_t)(gm + 8) * NG + gn] = p1;
        }
    }
}

// ---------------------------------------------------------------------------
// fused gemm2 v8: fp16 Xs (halved staging + LDS) + fp16 ker2 reg-prefetch.
// smem: As 5.1KB | Bs 2x10.2KB | Xs 2x5.4KB = ~36.5KB. 3 CTAs/SM.
// ---------------------------------------------------------------------------
#define SM_AS    0
#define SM_BS    5120
#define BS_BYTES 10240
#define SM_XS    (SM_BS + 2 * BS_BYTES)
#define XS_BYTES (68 * 40 * 2)
#define SM_TOT   (SM_XS + 2 * XS_BYTES)
#define BSTR     40

__global__ __launch_bounds__(256, 3) void gemm2_fused8(
    const float* __restrict__ bp, float* __restrict__ out)
{
    extern __shared__ __align__(16) uint8_t dsm[];
    __half* As = (__half*)(dsm + SM_AS);
    const uint32_t smb = (uint32_t)__cvta_generic_to_shared(dsm);

    const int tid = threadIdx.x;
    const int wid = tid >> 5, lane = tid & 31;
    const int gid = lane >> 2, tig = lane & 3;

    const int bx = blockIdx.x;
    const int whalf = bx & 1;
    const int b = (bx >> 1) & 3;
    const int h = bx >> 3;
    const int w0 = whalf * 64;
    const int c0 = whalf ? 31 : 0;

    const int wm = (wid & 3) * 16;
    const int wn = (wid >> 2) * 64;

    const int rA = (h - 1) >> 1, rB = (h + 1) >> 1;
    const bool vrA = h >= 1, vrB = h <= 126;

    const int awl = tid >> 2;
    const int w   = w0 + awl;
    const int ch0 = (tid & 3) * 8;
    const int par = ((h & 1) << 1) | (w & 1);
    const __half* kbase = g_ker16 + ((size_t)par * 4096 + (h >> 1) * 64 + (w >> 1)) * NG + ch0;
    const int colA = ((w - 1) >> 1) - c0, colB = ((w + 1) >> 1) - c0;
    const bool vcA = w >= 1, vcB = w <= 126;

    const int aRow = (lane & 7) + ((lane >> 3) & 1) * 8;
    const int aCol = ((lane >> 4) & 1) * 8;
    const int bRow = (lane & 7) + ((lane >> 4) & 1) * 8;
    const int bCol = ((lane >> 3) & 1) * 8;

    float c[8][4];
    #pragma unroll
    for (int j = 0; j < 8; ++j)
        #pragma unroll
        for (int e = 0; e < 4; ++e) c[j][e] = 0.0f;

    auto stage = [&](int buf, int kc) {
        // Xs: 2 src rows x 34 cols x 32 ch fp16 (272 cp16)
        #pragma unroll
        for (int q = 0; q < 2; ++q) {
            int s = q * 256 + tid;
            if (s < 272) {
                int pos = s >> 2, part = s & 3;
                int r = pos / 34, ci = pos - r * 34;
                int col = c0 + ci;
                bool ok = (r ? vrB : vrA) && (col < 64);
                int srow = r ? rB : rA; if (srow < 0) srow = 0;
                int scol = ok ? col : 0;
                const __half* src = &g_x16[(((size_t)b * 64 + srow) * 64 + scol) * CC + kc + part * 8];
                uint32_t dst = smb + SM_XS + (uint32_t)(buf * XS_BYTES + (pos * 40 + part * 8) * 2);
                cp16(dst, src, ok ? 16 : 0);
            }
        }
        // Bs: Wp fp16 128n x 32k (512 cp16)
        #pragma unroll
        for (int q = 0; q < 2; ++q) {
            int s = q * 256 + tid;
            int n = s >> 2, part = s & 3;
            const __half* src = g_WpT16 + (size_t)n * CC + kc + part * 8;
            uint32_t dst = smb + SM_BS + (uint32_t)(buf * BS_BYTES + (n * BSTR + part * 8) * 2);
            cp16(dst, src, 16);
        }
        CP_COMMIT();
    };

    uint4 kq[4];
    #pragma unroll
    for (int g = 0; g < 4; ++g) kq[g] = *(const uint4*)&kbase[g * 256];

    stage(0, 0);
    CP_WAIT0();
    __syncthreads();

    for (int chunk = 0; chunk < 8; ++chunk) {
        const int cur = chunk & 1;
        const int kc  = chunk * 32;

        // ---- build As from kq (regs) + fp16 Xs[cur] ----
        {
            const __half* Xb = (const __half*)(dsm + SM_XS + cur * XS_BYTES);
            float y[8];
            #pragma unroll
            for (int j = 0; j < 8; ++j) y[j] = 0.0f;
            #pragma unroll
            for (int g = 0; g < 4; ++g) {
                int  rr  = g >> 1;
                int  cr  = (g & 1) ? colB : colA;
                bool ok  = (g & 1) ? vcB : vcA;
                uint4 sv = make_uint4(0u, 0u, 0u, 0u);
                if (ok) sv = *(const uint4*)&Xb[(rr * 34 + cr) * 40 + ch0];
                const __half2* sh = (const __half2*)&sv;
                const __half2* kh = (const __half2*)&kq[g];
                #pragma unroll
                for (int p2 = 0; p2 < 4; ++p2) {
                    float2 kk = __half22float2(kh[p2]);
                    float2 ss = __half22float2(sh[p2]);
                    y[p2 * 2]     += kk.x * ss.x;
                    y[p2 * 2 + 1] += kk.y * ss.y;
                }
            }
            uint32_t hu[4];
            #pragma unroll
            for (int j2 = 0; j2 < 4; ++j2) {
                __half h0 = __float2half(y[j2 * 2]);
                __half h1 = __float2half(y[j2 * 2 + 1]);
                hu[j2] = (uint32_t)__half_as_ushort(h0) | ((uint32_t)__half_as_ushort(h1) << 16);
            }
            *(uint4*)&As[awl * BSTR + ch0] = make_uint4(hu[0], hu[1], hu[2], hu[3]);
        }
        __syncthreads();

        // ---- stage next + k prefetch + MMA ----
        if (chunk < 7) {
            stage(cur ^ 1, kc + 32);
            const __half* kbp = kbase + kc + 32;
            #pragma unroll
            for (int g = 0; g < 4; ++g) kq[g] = *(const uint4*)&kbp[g * 256];
        }
        {
            const uint32_t smAa = smb + SM_AS;
            const uint32_t smBb = smb + SM_BS + (uint32_t)(cur * BS_BYTES);
            #pragma unroll
            for (int ks2 = 0; ks2 < 2; ++ks2) {
                const int kb = ks2 * 16;
                uint32_t a[4];
                {
                    uint32_t adr = smAa + (uint32_t)((wm + aRow) * BSTR + kb + aCol) * 2;
                    ldsm_x4(a[0], a[1], a[2], a[3], adr);
                }
                #pragma unroll
                for (int nf = 0; nf < 8; nf += 2) {
                    uint32_t b0[2], b1[2];
                    uint32_t adr = smBb + (uint32_t)((wn + nf * 8 + bRow) * BSTR + kb + bCol) * 2;
                    ldsm_x4(b0[0], b0[1], b1[0], b1[1], adr);
                    mma16816h(c[nf],     a, b0);
                    mma16816h(c[nf + 1], a, b1);
                }
            }
        }
        CP_WAIT0();
        __syncthreads();
    }

    const int gm = b * 16384 + h * 128 + w0 + wm + gid;
    #pragma unroll
    for (int nf = 0; nf < 8; ++nf) {
        int gn = wn + nf * 8 + tig * 2;
        float bx2 = __ldg(&bp[gn]), by2 = __ldg(&bp[gn + 1]);
        float2 v0 = { c[nf][0] + bx2, c[nf][1] + by2 };
        float2 v1 = { c[nf][2] + bx2, c[nf][3] + by2 };
        *(float2*)&out[(size_t)gm * FF + gn]       = v0;
        *(float2*)&out[(size_t)(gm + 8) * FF + gn] = v1;
    }
}

// ---------------------------------------------------------------------------
extern "C" void kernel_launch(void* const* d_in, const int* in_sizes, int n_in,
                              void* d_out, int out_size)
{
    const float* main_in = (const float*)d_in[0];
    const float* W1 = (const float*)d_in[2];
    const float* b1 = (const float*)d_in[3];
    const float* W2 = (const float*)d_in[4];
    const float* b2 = (const float*)d_in[5];
    const float* W3 = (const float*)d_in[6];
    const float* b3 = (const float*)d_in[7];
    const float* W4 = (const float*)d_in[8];
    const float* b4 = (const float*)d_in[9];
    const float* Wo = (const float*)d_in[10];
    const float* bo = (const float*)d_in[11];
    const float* Wp = (const float*)d_in[12];
    const float* bp = (const float*)d_in[13];
    float* out = (float*)d_out;

    cudaFuncSetAttribute(gemm2_fused8, cudaFuncAttributeMaxDynamicSharedMemorySize, SM_TOT);

    const int prep_elems = 4 * NG * 32 + 4 * NG + FF * CC + 4096 + 4096 + 32;
    x2h_kernel<<<(BB * 64 * 64 * CC) / 1024, 256>>>(main_in);
    prep_kernel<<<(prep_elems + 255) / 256, 256>>>(Wo, bo, Wp, W1, b1);
    mlp_kernel<<<256, 256>>>(W2, b2, W3, b3, W4, b4);
    gemm1_kernel<<<dim3(128, 8), 256>>>();
    gemm2_fused8<<<1024, 256, SM_TOT>>>(bp, out);
}

// round 15
// speedup vs baseline: 1.0044x; 1.0044x over previous
#include <cuda_runtime.h>
#include <cuda_bf16.h>
#include <cuda_fp16.h>
#include <cstdint>
#include <math.h>

#define HT   128
#define CC   256
#define FF   128
#define BB   4
#define NU   32
#define NOUT 2304
#define NG   1024
#define PIF  3.14159265358979323846f

typedef __nv_bfloat16 bf16;

// ---------------- scratch globals ----------------
__device__ __align__(16) bf16   g_Wgh[4 * NG * 32];
__device__ __align__(16) bf16   g_Wgl[4 * NG * 32];
__device__ __align__(16) float  g_bg[4 * NG];
__device__ __align__(16) float  g_Hc[128 * 32];
__device__ __align__(16) float  g_Wc[128 * 32];
__device__ __align__(16) float  g_Cc[32];
__device__ __align__(16) bf16   g_x4h[(size_t)16384 * 32];
__device__ __align__(16) bf16   g_x4l[(size_t)16384 * 32];
__device__ __align__(16) __half g_WpT16[(size_t)FF * CC];     // [n][k] fp16
__device__ __align__(16) __half g_ker16[(size_t)16384 * NG];  // fp16 grouped kernels

__device__ __forceinline__ void split_bf(float v, bf16& hi, bf16& lo) {
    hi = __float2bfloat16(v);
    lo = __float2bfloat16(v - __bfloat162float(hi));
}
__device__ __forceinline__ void mma16816(float c[4], const uint32_t a[4], const uint32_t b[2]) {
    asm volatile(
        "mma.sync.aligned.m16n8k16.row.col.f32.bf16.bf16.f32 "
        "{%0,%1,%2,%3}, {%4,%5,%6,%7}, {%8,%9}, {%0,%1,%2,%3};"
        : "+f"(c[0]), "+f"(c[1]), "+f"(c[2]), "+f"(c[3])
        : "r"(a[0]), "r"(a[1]), "r"(a[2]), "r"(a[3]), "r"(b[0]), "r"(b[1]));
}
__device__ __forceinline__ void mma16816h(float c[4], const uint32_t a[4], const uint32_t b[2]) {
    asm volatile(
        "mma.sync.aligned.m16n8k16.row.col.f32.f16.f16.f32 "
        "{%0,%1,%2,%3}, {%4,%5,%6,%7}, {%8,%9}, {%0,%1,%2,%3};"
        : "+f"(c[0]), "+f"(c[1]), "+f"(c[2]), "+f"(c[3])
        : "r"(a[0]), "r"(a[1]), "r"(a[2]), "r"(a[3]), "r"(b[0]), "r"(b[1]));
}
__device__ __forceinline__ void ldsm_x4(uint32_t& r0, uint32_t& r1, uint32_t& r2, uint32_t& r3,
                                        uint32_t addr) {
    asm volatile("ldmatrix.sync.aligned.m8n8.x4.shared.b16 {%0,%1,%2,%3}, [%4];"
                 : "=r"(r0), "=r"(r1), "=r"(r2), "=r"(r3) : "r"(addr));
}
__device__ __forceinline__ int grp(int t, int par) { return (t == 0) ? 0 : (t == 2) ? 1 : (par ? 0 : 1); }

__device__ __forceinline__ void cp16(uint32_t dst, const void* src, int sz) {
    asm volatile("cp.async.cg.shared.global [%0], [%1], 16, %2;"
                 :: "r"(dst), "l"(src), "r"(sz));
}
#define CP_COMMIT() asm volatile("cp.async.commit_group;" ::: "memory")
#define CP_WAIT0()  asm volatile("cp.async.wait_group 0;" ::: "memory")

// ---------------------------------------------------------------------------
// prep
// ---------------------------------------------------------------------------
__global__ __launch_bounds__(256) void prep_kernel(
    const float* __restrict__ Wo, const float* __restrict__ bo,
    const float* __restrict__ Wp,
    const float* __restrict__ W1, const float* __restrict__ b1)
{
    int idx = blockIdx.x * 256 + threadIdx.x;
    if (idx < 4 * NG * 32) {
        int par = idx >> 15, rem = idx & 32767;
        int n = rem >> 5, k = rem & 31;
        int g = n >> 8, c = n & 255, gr = g >> 1, gc = g & 1;
        int ph = par >> 1, pw = par & 1;
        float s = 0.0f;
        #pragma unroll
        for (int tr = 0; tr < 3; ++tr)
            #pragma unroll
            for (int tc = 0; tc < 3; ++tc)
                if (grp(tr, ph) == gr && grp(tc, pw) == gc)
                    s += Wo[(size_t)k * NOUT + (tr * 3 + tc) * 256 + c];
        bf16 hi, lo; split_bf(s, hi, lo);
        g_Wgh[idx] = hi; g_Wgl[idx] = lo;
    } else if ((idx -= 4 * NG * 32) < 4 * NG) {
        int par = idx >> 10, n = idx & 1023;
        int g = n >> 8, c = n & 255, gr = g >> 1, gc = g & 1;
        int ph = par >> 1, pw = par & 1;
        float s = 0.0f;
        #pragma unroll
        for (int tr = 0; tr < 3; ++tr)
            #pragma unroll
            for (int tc = 0; tc < 3; ++tc)
                if (grp(tr, ph) == gr && grp(tc, pw) == gc)
                    s += bo[(tr * 3 + tc) * 256 + c];
        g_bg[idx] = s;
    } else if ((idx -= 4 * NG) < FF * CC) {
        int n = idx >> 8, k = idx & 255;
        g_WpT16[idx] = __float2half(Wp[(size_t)k * FF + n]);
    } else if ((idx -= FF * CC) < 4096) {
        int h = idx >> 5, j = idx & 31;
        float s = 0.0f;
        for (int i = 0; i < 25; ++i) {
            float f = 1.0f + (float)i * (1.0f / 24.0f);
            s += cosf(PIF * (2.0f * h * (1.0f / 127.0f) + 1.0f) * f) * W1[i * 32 + j];
        }
        g_Hc[idx] = s;
    } else if ((idx -= 4096) < 4096) {
        int w = idx >> 5, j = idx & 31;
        float s = 0.0f;
        for (int i = 0; i < 25; ++i) {
            float f = 1.0f + (float)i * (1.0f / 24.0f);
            s += cosf(PIF * (2.0f * w * (1.0f / 127.0f) + 1.0f) * f) * W1[(25 + i) * 32 + j];
        }
        g_Wc[idx] = s;
    } else if ((idx -= 4096) < 32) {
        int j = idx;
        float s = b1[j];
        for (int i = 0; i < 50; ++i) {
            float f = 1.0f + (float)(i % 25) * (1.0f / 24.0f);
            s += cosf(PIF * 5.0f * f) * W1[(50 + i) * 32 + j];
        }
        for (int i = 100; i < 118; ++i) s -= W1[i * 32 + j];
        g_Cc[j] = s;
    }
}

// ---------------------------------------------------------------------------
// mlp: 64 px/CTA (grid 256) -> x4 hi/lo, parity-major p'
// ---------------------------------------------------------------------------
__global__ __launch_bounds__(256) void mlp_kernel(
    const float* __restrict__ W2, const float* __restrict__ b2,
    const float* __restrict__ W3, const float* __restrict__ b3,
    const float* __restrict__ W4, const float* __restrict__ b4)
{
    __shared__ float xa[64][32];
    __shared__ float xb[64][32];
    const int tid = threadIdx.x;
    const int pix0 = blockIdx.x * 64;

    for (int o = tid; o < 2048; o += 256) {
        int p = o >> 5, j = o & 31;
        int pix = pix0 + p, h = pix >> 7, w = pix & 127;
        xa[p][j] = fmaxf(g_Hc[h * 32 + j] + g_Wc[w * 32 + j] + g_Cc[j], 0.0f);
    }
    __syncthreads();
    for (int o = tid; o < 2048; o += 256) {
        int p = o >> 5, j = o & 31;
        float s = b2[j];
        #pragma unroll
        for (int k = 0; k < NU; ++k) s += xa[p][k] * W2[k * NU + j];
        xb[p][j] = fmaxf(s, 0.0f);
    }
    __syncthreads();
    for (int o = tid; o < 2048; o += 256) {
        int p = o >> 5, j = o & 31;
        float s = b3[j];
        #pragma unroll
        for (int k = 0; k < NU; ++k) s += xb[p][k] * W3[k * NU + j];
        xa[p][j] = fmaxf(s, 0.0f);
    }
    __syncthreads();
    for (int o = tid; o < 2048; o += 256) {
        int p = o >> 5, j = o & 31;
        float s = b4[j];
        #pragma unroll
        for (int k = 0; k < NU; ++k) s += xa[p][k] * W4[k * NU + j];
        float v = fmaxf(s, 0.0f);
        int pix = pix0 + p, h = pix >> 7, w = pix & 127;
        int pp = (((h & 1) << 1) | (w & 1)) * 4096 + (h >> 1) * 64 + (w >> 1);
        bf16 hi, lo; split_bf(v, hi, lo);
        size_t o2 = (size_t)pp * 32 + j;
        g_x4h[o2] = hi; g_x4l[o2] = lo;
    }
}

// ---------------------------------------------------------------------------
// gemm1 v2: CTA tile 128m x 64n (warp 32x32), 3 CTAs/SM. grid (128, 16).
// ---------------------------------------------------------------------------
__global__ __launch_bounds__(256, 3) void gemm1_kernel()
{
    __shared__ __align__(16) bf16 As[128 * 72];
    __shared__ __align__(16) bf16 Bs[64 * 72];

    const int tid = threadIdx.x;
    const int wid = tid >> 5, lane = tid & 31;
    const int gid = lane >> 2, tig = lane & 3;
    const int m0 = blockIdx.x * 128, n0g = blockIdx.y * 64;
    const int par = blockIdx.x >> 5;
    const int wm0 = (wid & 3) * 32, wn0 = (wid >> 2) * 32;

    const bf16* WgH = g_Wgh + (size_t)par * NG * 32;
    const bf16* WgL = g_Wgl + (size_t)par * NG * 32;

    for (int i = tid; i < 512; i += 256) {
        int r = i >> 2, q = (i & 3) * 8;
        *(uint4*)&As[r * 72 + q]      = *(const uint4*)&g_x4h[(size_t)(m0 + r) * 32 + q];
        *(uint4*)&As[r * 72 + 32 + q] = *(const uint4*)&g_x4l[(size_t)(m0 + r) * 32 + q];
    }
    if (tid < 256) {
        int i = tid;
        int r = i >> 2, q = (i & 3) * 8;
        *(uint4*)&Bs[r * 72 + q]      = *(const uint4*)&WgH[(size_t)(n0g + r) * 32 + q];
        *(uint4*)&Bs[r * 72 + 32 + q] = *(const uint4*)&WgL[(size_t)(n0g + r) * 32 + q];
    }
    __syncthreads();

    const uint32_t smA = (uint32_t)__cvta_generic_to_shared(As);
    const uint32_t smB = (uint32_t)__cvta_generic_to_shared(Bs);
    const int aRow = (lane & 7) + ((lane >> 3) & 1) * 8;
    const int aCol = ((lane >> 4) & 1) * 8;
    const int bRow = (lane & 7) + ((lane >> 4) & 1) * 8;
    const int bCol = ((lane >> 3) & 1) * 8;

    float c[2][4][4];
    #pragma unroll
    for (int i = 0; i < 2; ++i)
        #pragma unroll
        for (int j = 0; j < 4; ++j)
            #pragma unroll
            for (int e = 0; e < 4; ++e) c[i][j][e] = 0.0f;

    #pragma unroll
    for (int ks = 0; ks < 2; ++ks) {
        const int kb = ks * 16;
        uint32_t aH[2][4], aL[2][4], bH[4][2], bL[4][2];
        #pragma unroll
        for (int mf = 0; mf < 2; ++mf) {
            uint32_t adr = smA + (uint32_t)((wm0 + mf * 16 + aRow) * 72 + kb + aCol) * 2;
            ldsm_x4(aH[mf][0], aH[mf][1], aH[mf][2], aH[mf][3], adr);
            ldsm_x4(aL[mf][0], aL[mf][1], aL[mf][2], aL[mf][3], adr + 64);
        }
        #pragma unroll
        for (int nf = 0; nf < 4; nf += 2) {
            uint32_t adr = smB + (uint32_t)((wn0 + nf * 8 + bRow) * 72 + kb + bCol) * 2;
            ldsm_x4(bH[nf][0], bH[nf][1], bH[nf + 1][0], bH[nf + 1][1], adr);
            ldsm_x4(bL[nf][0], bL[nf][1], bL[nf + 1][0], bL[nf + 1][1], adr + 64);
        }
        #pragma unroll
        for (int mf = 0; mf < 2; ++mf)
            #pragma unroll
            for (int nf = 0; nf < 4; ++nf) {
                mma16816(c[mf][nf], aH[mf], bH[nf]);
                mma16816(c[mf][nf], aH[mf], bL[nf]);
                mma16816(c[mf][nf], aL[mf], bH[nf]);
            }
    }

    const float* bgp = g_bg + par * NG;
    #pragma unroll
    for (int mf = 0; mf < 2; ++mf) {
        int gm = m0 + wm0 + mf * 16 + gid;
        #pragma unroll
        for (int nf = 0; nf < 4; ++nf) {
            int gn = n0g + wn0 + nf * 8 + tig * 2;
            float bx = __ldg(&bgp[gn]), by = __ldg(&bgp[gn + 1]);
            __half2 p0 = __floats2half2_rn(c[mf][nf][0] + bx, c[mf][nf][1] + by);
            __half2 p1 = __floats2half2_rn(c[mf][nf][2] + bx, c[mf][nf][3] + by);
            *(__half2*)&g_ker16[(size_t)gm * NG + gn]       = p0;
            *(__half2*)&g_ker16[(size_t)(gm + 8) * NG + gn] = p1;
        }
    }
}

// ---------------------------------------------------------------------------
// fused gemm2 (R13 v7): fp32 main_in staging + fp16 ker reg-prefetch.
// Half-row CTAs (64 m). smem: As 5.1KB | Bs 2x10.2KB | Xs 2x9.8KB = ~45KB.
// ---------------------------------------------------------------------------
#define SM_AS    0
#define SM_BS    5120
#define BS_BYTES 10240
#define SM_XS    (SM_BS + 2 * BS_BYTES)
#define SM_TOT   (SM_XS + 19584)
#define XS_FLTS  2448
#define BSTR     40

__global__ __launch_bounds__(256, 3) void gemm2_fused7(
    const float* __restrict__ main_in,
    const float* __restrict__ bp, float* __restrict__ out)
{
    extern __shared__ __align__(16) uint8_t dsm[];
    __half* As = (__half*)(dsm + SM_AS);
    float*  Xs = (float*)(dsm + SM_XS);
    const uint32_t smb = (uint32_t)__cvta_generic_to_shared(dsm);

    const int tid = threadIdx.x;
    const int wid = tid >> 5, lane = tid & 31;
    const int gid = lane >> 2, tig = lane & 3;

    const int bx = blockIdx.x;
    const int whalf = bx & 1;
    const int b = (bx >> 1) & 3;
    const int h = bx >> 3;
    const int w0 = whalf * 64;
    const int c0 = whalf ? 31 : 0;

    const int wm = (wid & 3) * 16;
    const int wn = (wid >> 2) * 64;

    const int rA = (h - 1) >> 1, rB = (h + 1) >> 1;
    const bool vrA = h >= 1, vrB = h <= 126;

    const int awl = tid >> 2;
    const int w   = w0 + awl;
    const int ch0 = (tid & 3) * 8;
    const int par = ((h & 1) << 1) | (w & 1);
    const __half* kbase = g_ker16 + ((size_t)par * 4096 + (h >> 1) * 64 + (w >> 1)) * NG + ch0;
    const int colA = ((w - 1) >> 1) - c0, colB = ((w + 1) >> 1) - c0;
    const bool vcA = w >= 1, vcB = w <= 126;

    const int aRow = (lane & 7) + ((lane >> 3) & 1) * 8;
    const int aCol = ((lane >> 4) & 1) * 8;
    const int bRow = (lane & 7) + ((lane >> 4) & 1) * 8;
    const int bCol = ((lane >> 3) & 1) * 8;

    float c[8][4];
    #pragma unroll
    for (int j = 0; j < 8; ++j)
        #pragma unroll
        for (int e = 0; e < 4; ++e) c[j][e] = 0.0f;

    auto stage = [&](int buf, int kc) {
        #pragma unroll
        for (int q = 0; q < 3; ++q) {
            int s = q * 256 + tid;
            if (s < 544) {
                int pos = s >> 3, qq = s & 7;
                int r = pos / 34, ci = pos - r * 34;
                int col = c0 + ci;
                bool ok = (r ? vrB : vrA) && (col < 64);
                int srow = r ? rB : rA; if (srow < 0) srow = 0;
                int scol = ok ? col : 0;
                const float* src = &main_in[(((size_t)b * 64 + srow) * 64 + scol) * CC + kc + qq * 4];
                uint32_t dst = smb + SM_XS + (uint32_t)(buf * XS_FLTS + pos * 36 + qq * 4) * 4;
                cp16(dst, src, ok ? 16 : 0);
            }
        }
        #pragma unroll
        for (int q = 0; q < 2; ++q) {
            int s = q * 256 + tid;
            int n = s >> 2, part = s & 3;
            const __half* src = g_WpT16 + (size_t)n * CC + kc + part * 8;
            uint32_t dst = smb + SM_BS + (uint32_t)(buf * BS_BYTES + (n * BSTR + part * 8) * 2);
            cp16(dst, src, 16);
        }
        CP_COMMIT();
    };

    uint4 kq[4];
    #pragma unroll
    for (int g = 0; g < 4; ++g) kq[g] = *(const uint4*)&kbase[g * 256];

    stage(0, 0);
    CP_WAIT0();
    __syncthreads();

    for (int chunk = 0; chunk < 8; ++chunk) {
        const int cur = chunk & 1;
        const int kc  = chunk * 32;

        // ---- build As from kq (regs) + Xs[cur] ----
        {
            const float* Xb = Xs + cur * XS_FLTS;
            float y[8];
            #pragma unroll
            for (int j = 0; j < 8; ++j) y[j] = 0.0f;
            #pragma unroll
            for (int g = 0; g < 4; ++g) {
                int  rr  = g >> 1;
                int  cr  = (g & 1) ? colB : colA;
                bool ok  = (g & 1) ? vcB : vcA;
                float4 s0 = make_float4(0.f, 0.f, 0.f, 0.f), s1 = s0;
                if (ok) {
                    s0 = *(const float4*)&Xb[(rr * 34 + cr) * 36 + ch0];
                    s1 = *(const float4*)&Xb[(rr * 34 + cr) * 36 + ch0 + 4];
                }
                const __half2* kh = (const __half2*)&kq[g];
                float2 k01 = __half22float2(kh[0]);
                float2 k23 = __half22float2(kh[1]);
                float2 k45 = __half22float2(kh[2]);
                float2 k67 = __half22float2(kh[3]);
                y[0] += k01.x * s0.x; y[1] += k01.y * s0.y;
                y[2] += k23.x * s0.z; y[3] += k23.y * s0.w;
                y[4] += k45.x * s1.x; y[5] += k45.y * s1.y;
                y[6] += k67.x * s1.z; y[7] += k67.y * s1.w;
            }
            uint32_t hu[4];
            #pragma unroll
            for (int j2 = 0; j2 < 4; ++j2) {
                __half h0 = __float2half(y[j2 * 2]);
                __half h1 = __float2half(y[j2 * 2 + 1]);
                hu[j2] = (uint32_t)__half_as_ushort(h0) | ((uint32_t)__half_as_ushort(h1) << 16);
            }
            *(uint4*)&As[awl * BSTR + ch0] = make_uint4(hu[0], hu[1], hu[2], hu[3]);
        }
        __syncthreads();

        // ---- stage next + k prefetch (regs) + MMA ----
        if (chunk < 7) {
            stage(cur ^ 1, kc + 32);
            const __half* kbp = kbase + kc + 32;
            #pragma unroll
            for (int g = 0; g < 4; ++g) kq[g] = *(const uint4*)&kbp[g * 256];
        }
        {
            const uint32_t smAa = smb + SM_AS;
            const uint32_t smBb = smb + SM_BS + (uint32_t)(cur * BS_BYTES);
            #pragma unroll
            for (int ks2 = 0; ks2 < 2; ++ks2) {
                const int kb = ks2 * 16;
                uint32_t a[4];
                {
                    uint32_t adr = smAa + (uint32_t)((wm + aRow) * BSTR + kb + aCol) * 2;
                    ldsm_x4(a[0], a[1], a[2], a[3], adr);
                }
                #pragma unroll
                for (int nf = 0; nf < 8; nf += 2) {
                    uint32_t b0[2], b1[2];
                    uint32_t adr = smBb + (uint32_t)((wn + nf * 8 + bRow) * BSTR + kb + bCol) * 2;
                    ldsm_x4(b0[0], b0[1], b1[0], b1[1], adr);
                    mma16816h(c[nf],     a, b0);
                    mma16816h(c[nf + 1], a, b1);
                }
            }
        }
        CP_WAIT0();
        __syncthreads();
    }

    const int gm = b * 16384 + h * 128 + w0 + wm + gid;
    #pragma unroll
    for (int nf = 0; nf < 8; ++nf) {
        int gn = wn + nf * 8 + tig * 2;
        float bx2 = __ldg(&bp[gn]), by2 = __ldg(&bp[gn + 1]);
        float2 v0 = { c[nf][0] + bx2, c[nf][1] + by2 };
        float2 v1 = { c[nf][2] + bx2, c[nf][3] + by2 };
        *(float2*)&out[(size_t)gm * FF + gn]       = v0;
        *(float2*)&out[(size_t)(gm + 8) * FF + gn] = v1;
    }
}

// ---------------------------------------------------------------------------
extern "C" void kernel_launch(void* const* d_in, const int* in_sizes, int n_in,
                              void* d_out, int out_size)
{
    const float* main_in = (const float*)d_in[0];
    const float* W1 = (const float*)d_in[2];
    const float* b1 = (const float*)d_in[3];
    const float* W2 = (const float*)d_in[4];
    const float* b2 = (const float*)d_in[5];
    const float* W3 = (const float*)d_in[6];
    const float* b3 = (const float*)d_in[7];
    const float* W4 = (const float*)d_in[8];
    const float* b4 = (const float*)d_in[9];
    const float* Wo = (const float*)d_in[10];
    const float* bo = (const float*)d_in[11];
    const float* Wp = (const float*)d_in[12];
    const float* bp = (const float*)d_in[13];
    float* out = (float*)d_out;

    cudaFuncSetAttribute(gemm2_fused7, cudaFuncAttributeMaxDynamicSharedMemorySize, SM_TOT);

    const int prep_elems = 4 * NG * 32 + 4 * NG + FF * CC + 4096 + 4096 + 32;
    prep_kernel<<<(prep_elems + 255) / 256, 256>>>(Wo, bo, Wp, W1, b1);
    mlp_kernel<<<256, 256>>>(W2, b2, W3, b3, W4, b4);
    gemm1_kernel<<<dim3(128, 16), 256>>>();
    gemm2_fused7<<<1024, 256, SM_TOT>>>(main_in, bp, out);
}

// round 16
// speedup vs baseline: 1.1033x; 1.0984x over previous
#include <cuda_runtime.h>
#include <cuda_bf16.h>
#include <cuda_fp16.h>
#include <cstdint>
#include <math.h>

#define HT   128
#define CC   256
#define FF   128
#define BB   4
#define NU   32
#define NOUT 2304
#define NG   1024
#define PIF  3.14159265358979323846f

typedef __nv_bfloat16 bf16;

// ---------------- scratch globals ----------------
__device__ __align__(16) bf16   g_Wgh[4 * NG * 32];
__device__ __align__(16) bf16   g_Wgl[4 * NG * 32];
__device__ __align__(16) float  g_bg[4 * NG];
__device__ __align__(16) float  g_Hc[128 * 32];
__device__ __align__(16) float  g_Wc[128 * 32];
__device__ __align__(16) float  g_Cc[32];
__device__ __align__(16) bf16   g_x4h[(size_t)16384 * 32];
__device__ __align__(16) bf16   g_x4l[(size_t)16384 * 32];
__device__ __align__(16) __half g_WpT16[(size_t)FF * CC];
// transposed ker: [h][chunk][g][w][c32]  (h*8+cc)*4+g blocks of 4096 halves
__device__ __align__(16) __half g_kerT[(size_t)128 * 8 * 4 * 128 * 32];

__device__ __forceinline__ void split_bf(float v, bf16& hi, bf16& lo) {
    hi = __float2bfloat16(v);
    lo = __float2bfloat16(v - __bfloat162float(hi));
}
__device__ __forceinline__ void mma16816(float c[4], const uint32_t a[4], const uint32_t b[2]) {
    asm volatile(
        "mma.sync.aligned.m16n8k16.row.col.f32.bf16.bf16.f32 "
        "{%0,%1,%2,%3}, {%4,%5,%6,%7}, {%8,%9}, {%0,%1,%2,%3};"
        : "+f"(c[0]), "+f"(c[1]), "+f"(c[2]), "+f"(c[3])
        : "r"(a[0]), "r"(a[1]), "r"(a[2]), "r"(a[3]), "r"(b[0]), "r"(b[1]));
}
__device__ __forceinline__ void mma16816h(float c[4], const uint32_t a[4], const uint32_t b[2]) {
    asm volatile(
        "mma.sync.aligned.m16n8k16.row.col.f32.f16.f16.f32 "
        "{%0,%1,%2,%3}, {%4,%5,%6,%7}, {%8,%9}, {%0,%1,%2,%3};"
        : "+f"(c[0]), "+f"(c[1]), "+f"(c[2]), "+f"(c[3])
        : "r"(a[0]), "r"(a[1]), "r"(a[2]), "r"(a[3]), "r"(b[0]), "r"(b[1]));
}
__device__ __forceinline__ void ldsm_x4(uint32_t& r0, uint32_t& r1, uint32_t& r2, uint32_t& r3,
                                        uint32_t addr) {
    asm volatile("ldmatrix.sync.aligned.m8n8.x4.shared.b16 {%0,%1,%2,%3}, [%4];"
                 : "=r"(r0), "=r"(r1), "=r"(r2), "=r"(r3) : "r"(addr));
}
__device__ __forceinline__ int grp(int t, int par) { return (t == 0) ? 0 : (t == 2) ? 1 : (par ? 0 : 1); }

__device__ __forceinline__ void cp16(uint32_t dst, const void* src, int sz) {
    asm volatile("cp.async.cg.shared.global [%0], [%1], 16, %2;"
                 :: "r"(dst), "l"(src), "r"(sz));
}
#define CP_COMMIT() asm volatile("cp.async.commit_group;" ::: "memory")
#define CP_WAIT0()  asm volatile("cp.async.wait_group 0;" ::: "memory")

// ---------------------------------------------------------------------------
// prep
// ---------------------------------------------------------------------------
__global__ __launch_bounds__(256) void prep_kernel(
    const float* __restrict__ Wo, const float* __restrict__ bo,
    const float* __restrict__ Wp,
    const float* __restrict__ W1, const float* __restrict__ b1)
{
    int idx = blockIdx.x * 256 + threadIdx.x;
    if (idx < 4 * NG * 32) {
        int par = idx >> 15, rem = idx & 32767;
        int n = rem >> 5, k = rem & 31;
        int g = n >> 8, c = n & 255, gr = g >> 1, gc = g & 1;
        int ph = par >> 1, pw = par & 1;
        float s = 0.0f;
        #pragma unroll
        for (int tr = 0; tr < 3; ++tr)
            #pragma unroll
            for (int tc = 0; tc < 3; ++tc)
                if (grp(tr, ph) == gr && grp(tc, pw) == gc)
                    s += Wo[(size_t)k * NOUT + (tr * 3 + tc) * 256 + c];
        bf16 hi, lo; split_bf(s, hi, lo);
        g_Wgh[idx] = hi; g_Wgl[idx] = lo;
    } else if ((idx -= 4 * NG * 32) < 4 * NG) {
        int par = idx >> 10, n = idx & 1023;
        int g = n >> 8, c = n & 255, gr = g >> 1, gc = g & 1;
        int ph = par >> 1, pw = par & 1;
        float s = 0.0f;
        #pragma unroll
        for (int tr = 0; tr < 3; ++tr)
            #pragma unroll
            for (int tc = 0; tc < 3; ++tc)
                if (grp(tr, ph) == gr && grp(tc, pw) == gc)
                    s += bo[(tr * 3 + tc) * 256 + c];
        g_bg[idx] = s;
    } else if ((idx -= 4 * NG) < FF * CC) {
        int n = idx >> 8, k = idx & 255;
        g_WpT16[idx] = __float2half(Wp[(size_t)k * FF + n]);
    } else if ((idx -= FF * CC) < 4096) {
        int h = idx >> 5, j = idx & 31;
        float s = 0.0f;
        for (int i = 0; i < 25; ++i) {
            float f = 1.0f + (float)i * (1.0f / 24.0f);
            s += cosf(PIF * (2.0f * h * (1.0f / 127.0f) + 1.0f) * f) * W1[i * 32 + j];
        }
        g_Hc[idx] = s;
    } else if ((idx -= 4096) < 4096) {
        int w = idx >> 5, j = idx & 31;
        float s = 0.0f;
        for (int i = 0; i < 25; ++i) {
            float f = 1.0f + (float)i * (1.0f / 24.0f);
            s += cosf(PIF * (2.0f * w * (1.0f / 127.0f) + 1.0f) * f) * W1[(25 + i) * 32 + j];
        }
        g_Wc[idx] = s;
    } else if ((idx -= 4096) < 32) {
        int j = idx;
        float s = b1[j];
        for (int i = 0; i < 50; ++i) {
            float f = 1.0f + (float)(i % 25) * (1.0f / 24.0f);
            s += cosf(PIF * 5.0f * f) * W1[(50 + i) * 32 + j];
        }
        for (int i = 100; i < 118; ++i) s -= W1[i * 32 + j];
        g_Cc[j] = s;
    }
}

// ---------------------------------------------------------------------------
// mlp (R13 config: 16 px/CTA, grid 1024)
// ---------------------------------------------------------------------------
__global__ __launch_bounds__(256) void mlp_kernel(
    const float* __restrict__ W2, const float* __restrict__ b2,
    const float* __restrict__ W3, const float* __restrict__ b3,
    const float* __restrict__ W4, const float* __restrict__ b4)
{
    __shared__ float xa[16][32];
    __shared__ float xb[16][32];
    const int tid = threadIdx.x;
    const int pix0 = blockIdx.x * 16;

    for (int o = tid; o < 512; o += 256) {
        int p = o >> 5, j = o & 31;
        int pix = pix0 + p, h = pix >> 7, w = pix & 127;
        xa[p][j] = fmaxf(g_Hc[h * 32 + j] + g_Wc[w * 32 + j] + g_Cc[j], 0.0f);
    }
    __syncthreads();
    for (int o = tid; o < 512; o += 256) {
        int p = o >> 5, j = o & 31;
        float s = b2[j];
        #pragma unroll
        for (int k = 0; k < NU; ++k) s += xa[p][k] * W2[k * NU + j];
        xb[p][j] = fmaxf(s, 0.0f);
    }
    __syncthreads();
    for (int o = tid; o < 512; o += 256) {
        int p = o >> 5, j = o & 31;
        float s = b3[j];
        #pragma unroll
        for (int k = 0; k < NU; ++k) s += xb[p][k] * W3[k * NU + j];
        xa[p][j] = fmaxf(s, 0.0f);
    }
    __syncthreads();
    for (int o = tid; o < 512; o += 256) {
        int p = o >> 5, j = o & 31;
        float s = b4[j];
        #pragma unroll
        for (int k = 0; k < NU; ++k) s += xa[p][k] * W4[k * NU + j];
        float v = fmaxf(s, 0.0f);
        int pix = pix0 + p, h = pix >> 7, w = pix & 127;
        int pp = (((h & 1) << 1) | (w & 1)) * 4096 + (h >> 1) * 64 + (w >> 1);
        bf16 hi, lo; split_bf(v, hi, lo);
        size_t o2 = (size_t)pp * 32 + j;
        g_x4h[o2] = hi; g_x4l[o2] = lo;
    }
}

// ---------------------------------------------------------------------------
// gemm1 (R13 config, 128x128 tile) with TRANSPOSED fp16 epilogue -> g_kerT
// ---------------------------------------------------------------------------
__global__ __launch_bounds__(256) void gemm1_kernel()
{
    __shared__ __align__(16) bf16 As[128 * 72];
    __shared__ __align__(16) bf16 Bs[128 * 72];

    const int tid = threadIdx.x;
    const int wid = tid >> 5, lane = tid & 31;
    const int gid = lane >> 2, tig = lane & 3;
    const int m0 = blockIdx.x * 128, n0g = blockIdx.y * 128;
    const int par = blockIdx.x >> 5;
    const int wm0 = (wid & 3) * 32, wn0 = (wid >> 2) * 64;

    const bf16* WgH = g_Wgh + (size_t)par * NG * 32;
    const bf16* WgL = g_Wgl + (size_t)par * NG * 32;

    for (int i = tid; i < 512; i += 256) {
        int r = i >> 2, q = (i & 3) * 8;
        *(uint4*)&As[r * 72 + q]      = *(const uint4*)&g_x4h[(size_t)(m0 + r) * 32 + q];
        *(uint4*)&As[r * 72 + 32 + q] = *(const uint4*)&g_x4l[(size_t)(m0 + r) * 32 + q];
        *(uint4*)&Bs[r * 72 + q]      = *(const uint4*)&WgH[(size_t)(n0g + r) * 32 + q];
        *(uint4*)&Bs[r * 72 + 32 + q] = *(const uint4*)&WgL[(size_t)(n0g + r) * 32 + q];
    }
    __syncthreads();

    const uint32_t smA = (uint32_t)__cvta_generic_to_shared(As);
    const uint32_t smB = (uint32_t)__cvta_generic_to_shared(Bs);
    const int aRow = (lane & 7) + ((lane >> 3) & 1) * 8;
    const int aCol = ((lane >> 4) & 1) * 8;
    const int bRow = (lane & 7) + ((lane >> 4) & 1) * 8;
    const int bCol = ((lane >> 3) & 1) * 8;

    float c[2][8][4];
    #pragma unroll
    for (int i = 0; i < 2; ++i)
        #pragma unroll
        for (int j = 0; j < 8; ++j)
            #pragma unroll
            for (int e = 0; e < 4; ++e) c[i][j][e] = 0.0f;

    #pragma unroll
    for (int ks = 0; ks < 2; ++ks) {
        const int kb = ks * 16;
        uint32_t aH[2][4], aL[2][4], bH[8][2], bL[8][2];
        #pragma unroll
        for (int mf = 0; mf < 2; ++mf) {
            uint32_t adr = smA + (uint32_t)((wm0 + mf * 16 + aRow) * 72 + kb + aCol) * 2;
            ldsm_x4(aH[mf][0], aH[mf][1], aH[mf][2], aH[mf][3], adr);
            ldsm_x4(aL[mf][0], aL[mf][1], aL[mf][2], aL[mf][3], adr + 64);
        }
        #pragma unroll
        for (int nf = 0; nf < 8; nf += 2) {
            uint32_t adr = smB + (uint32_t)((wn0 + nf * 8 + bRow) * 72 + kb + bCol) * 2;
            ldsm_x4(bH[nf][0], bH[nf][1], bH[nf + 1][0], bH[nf + 1][1], adr);
            ldsm_x4(bL[nf][0], bL[nf][1], bL[nf + 1][0], bL[nf + 1][1], adr + 64);
        }
        #pragma unroll
        for (int mf = 0; mf < 2; ++mf)
            #pragma unroll
            for (int nf = 0; nf < 8; ++nf) {
                mma16816(c[mf][nf], aH[mf], bH[nf]);
                mma16816(c[mf][nf], aH[mf], bL[nf]);
                mma16816(c[mf][nf], aL[mf], bH[nf]);
            }
    }

    // transposed epilogue: g_kerT[((h*8+cc)*4+g)*4096 + w*32 + c32]
    const float* bgp = g_bg + par * NG;
    const int parh = par >> 1, parw = par & 1;
    #pragma unroll
    for (int mf = 0; mf < 2; ++mf) {
        #pragma unroll
        for (int half8 = 0; half8 < 2; ++half8) {
            int gm = m0 + wm0 + mf * 16 + gid + half8 * 8;
            int rem = gm & 4095;
            int hh = (((rem >> 6)) << 1) | parh;
            int ww = ((rem & 63) << 1) | parw;
            #pragma unroll
            for (int nf = 0; nf < 8; ++nf) {
                int gn = n0g + wn0 + nf * 8 + tig * 2;
                int g = gn >> 8, cg = gn & 255;
                int cc = cg >> 5, c32 = cg & 31;
                float bx = __ldg(&bgp[gn]), by = __ldg(&bgp[gn + 1]);
                float v0 = c[mf][nf][half8 * 2 + 0] + bx;
                float v1 = c[mf][nf][half8 * 2 + 1] + by;
                __half2 p = __floats2half2_rn(v0, v1);
                size_t addr = ((size_t)((hh * 8 + cc) * 4 + g) << 12) + ww * 32 + c32;
                *(__half2*)&g_kerT[addr] = p;
            }
        }
    }
}

// ---------------------------------------------------------------------------
// fused gemm2 v9: transposed coalesced ker loads, 4 CTAs/SM.
// Half-row CTAs (64 m). smem: As 5.1KB | Bs 2x10.2KB | Xs 2x9.8KB = ~45KB.
// ---------------------------------------------------------------------------
#define SM_AS    0
#define SM_BS    5120
#define BS_BYTES 10240
#define SM_XS    (SM_BS + 2 * BS_BYTES)
#define SM_TOT   (SM_XS + 19584)
#define XS_FLTS  2448
#define BSTR     40

__global__ __launch_bounds__(256, 4) void gemm2_fused9(
    const float* __restrict__ main_in,
    const float* __restrict__ bp, float* __restrict__ out)
{
    extern __shared__ __align__(16) uint8_t dsm[];
    __half* As = (__half*)(dsm + SM_AS);
    float*  Xs = (float*)(dsm + SM_XS);
    const uint32_t smb = (uint32_t)__cvta_generic_to_shared(dsm);

    const int tid = threadIdx.x;
    const int wid = tid >> 5, lane = tid & 31;
    const int gid = lane >> 2, tig = lane & 3;

    const int bx = blockIdx.x;
    const int whalf = bx & 1;
    const int b = (bx >> 1) & 3;
    const int h = bx >> 3;
    const int w0 = whalf * 64;
    const int c0 = whalf ? 31 : 0;

    const int wm = (wid & 3) * 16;
    const int wn = (wid >> 2) * 64;

    const int rA = (h - 1) >> 1, rB = (h + 1) >> 1;
    const bool vrA = h >= 1, vrB = h <= 126;

    const int awl = tid >> 2;
    const int w   = w0 + awl;
    const int ch0 = (tid & 3) * 8;
    // transposed ker base for this thread: +((h*8+cc)*4+g)*4096 + w*32 + ch0
    const __half* kTb = g_kerT + ((size_t)(h * 8) << 14) + w * 32 + ch0;
    const int colA = ((w - 1) >> 1) - c0, colB = ((w + 1) >> 1) - c0;
    const bool vcA = w >= 1, vcB = w <= 126;

    const int aRow = (lane & 7) + ((lane >> 3) & 1) * 8;
    const int aCol = ((lane >> 4) & 1) * 8;
    const int bRow = (lane & 7) + ((lane >> 4) & 1) * 8;
    const int bCol = ((lane >> 3) & 1) * 8;

    float c[8][4];
    #pragma unroll
    for (int j = 0; j < 8; ++j)
        #pragma unroll
        for (int e = 0; e < 4; ++e) c[j][e] = 0.0f;

    auto stage = [&](int buf, int kc) {
        #pragma unroll
        for (int q = 0; q < 3; ++q) {
            int s = q * 256 + tid;
            if (s < 544) {
                int pos = s >> 3, qq = s & 7;
                int r = pos / 34, ci = pos - r * 34;
                int col = c0 + ci;
                bool ok = (r ? vrB : vrA) && (col < 64);
                int srow = r ? rB : rA; if (srow < 0) srow = 0;
                int scol = ok ? col : 0;
                const float* src = &main_in[(((size_t)b * 64 + srow) * 64 + scol) * CC + kc + qq * 4];
                uint32_t dst = smb + SM_XS + (uint32_t)(buf * XS_FLTS + pos * 36 + qq * 4) * 4;
                cp16(dst, src, ok ? 16 : 0);
            }
        }
        #pragma unroll
        for (int q = 0; q < 2; ++q) {
            int s = q * 256 + tid;
            int n = s >> 2, part = s & 3;
            const __half* src = g_WpT16 + (size_t)n * CC + kc + part * 8;
            uint32_t dst = smb + SM_BS + (uint32_t)(buf * BS_BYTES + (n * BSTR + part * 8) * 2);
            cp16(dst, src, 16);
        }
        CP_COMMIT();
    };

    stage(0, 0);
    CP_WAIT0();
    __syncthreads();

    for (int chunk = 0; chunk < 8; ++chunk) {
        const int cur = chunk & 1;
        const int kc  = chunk * 32;

        // ---- build As: coalesced ker loads + Xs[cur] ----
        {
            const float* Xb = Xs + cur * XS_FLTS;
            const __half* kT = kTb + ((size_t)chunk << 14);
            float y[8];
            #pragma unroll
            for (int j = 0; j < 8; ++j) y[j] = 0.0f;
            #pragma unroll
            for (int g = 0; g < 4; ++g) {
                uint4 kv = *(const uint4*)&kT[(size_t)g << 12];
                int  rr  = g >> 1;
                int  cr  = (g & 1) ? colB : colA;
                bool ok  = (g & 1) ? vcB : vcA;
                float4 s0 = make_float4(0.f, 0.f, 0.f, 0.f), s1 = s0;
                if (ok) {
                    s0 = *(const float4*)&Xb[(rr * 34 + cr) * 36 + ch0];
                    s1 = *(const float4*)&Xb[(rr * 34 + cr) * 36 + ch0 + 4];
                }
                const __half2* kh = (const __half2*)&kv;
                float2 k01 = __half22float2(kh[0]);
                float2 k23 = __half22float2(kh[1]);
                float2 k45 = __half22float2(kh[2]);
                float2 k67 = __half22float2(kh[3]);
                y[0] += k01.x * s0.x; y[1] += k01.y * s0.y;
                y[2] += k23.x * s0.z; y[3] += k23.y * s0.w;
                y[4] += k45.x * s1.x; y[5] += k45.y * s1.y;
                y[6] += k67.x * s1.z; y[7] += k67.y * s1.w;
            }
            uint32_t hu[4];
            #pragma unroll
            for (int j2 = 0; j2 < 4; ++j2) {
                __half h0 = __float2half(y[j2 * 2]);
                __half h1 = __float2half(y[j2 * 2 + 1]);
                hu[j2] = (uint32_t)__half_as_ushort(h0) | ((uint32_t)__half_as_ushort(h1) << 16);
            }
            *(uint4*)&As[awl * BSTR + ch0] = make_uint4(hu[0], hu[1], hu[2], hu[3]);
        }
        __syncthreads();

        // ---- stage next + MMA ----
        if (chunk < 7) stage(cur ^ 1, kc + 32);
        {
            const uint32_t smAa = smb + SM_AS;
            const uint32_t smBb = smb + SM_BS + (uint32_t)(cur * BS_BYTES);
            #pragma unroll
            for (int ks2 = 0; ks2 < 2; ++ks2) {
                const int kb = ks2 * 16;
                uint32_t a[4];
                {
                    uint32_t adr = smAa + (uint32_t)((wm + aRow) * BSTR + kb + aCol) * 2;
                    ldsm_x4(a[0], a[1], a[2], a[3], adr);
                }
                #pragma unroll
                for (int nf = 0; nf < 8; nf += 2) {
                    uint32_t b0[2], b1[2];
                    uint32_t adr = smBb + (uint32_t)((wn + nf * 8 + bRow) * BSTR + kb + bCol) * 2;
                    ldsm_x4(b0[0], b0[1], b1[0], b1[1], adr);
                    mma16816h(c[nf],     a, b0);
                    mma16816h(c[nf + 1], a, b1);
                }
            }
        }
        CP_WAIT0();
        __syncthreads();
    }

    const int gm = b * 16384 + h * 128 + w0 + wm + gid;
    #pragma unroll
    for (int nf = 0; nf < 8; ++nf) {
        int gn = wn + nf * 8 + tig * 2;
        float bx2 = __ldg(&bp[gn]), by2 = __ldg(&bp[gn + 1]);
        float2 v0 = { c[nf][0] + bx2, c[nf][1] + by2 };
        float2 v1 = { c[nf][2] + bx2, c[nf][3] + by2 };
        *(float2*)&out[(size_t)gm * FF + gn]       = v0;
        *(float2*)&out[(size_t)(gm + 8) * FF + gn] = v1;
    }
}

// ---------------------------------------------------------------------------
extern "C" void kernel_launch(void* const* d_in, const int* in_sizes, int n_in,
                              void* d_out, int out_size)
{
    const float* main_in = (const float*)d_in[0];
    const float* W1 = (const float*)d_in[2];
    const float* b1 = (const float*)d_in[3];
    const float* W2 = (const float*)d_in[4];
    const float* b2 = (const float*)d_in[5];
    const float* W3 = (const float*)d_in[6];
    const float* b3 = (const float*)d_in[7];
    const float* W4 = (const float*)d_in[8];
    const float* b4 = (const float*)d_in[9];
    const float* Wo = (const float*)d_in[10];
    const float* bo = (const float*)d_in[11];
    const float* Wp = (const float*)d_in[12];
    const float* bp = (const float*)d_in[13];
    float* out = (float*)d_out;

    cudaFuncSetAttribute(gemm2_fused9, cudaFuncAttributeMaxDynamicSharedMemorySize, SM_TOT);

    const int prep_elems = 4 * NG * 32 + 4 * NG + FF * CC + 4096 + 4096 + 32;
    prep_kernel<<<(prep_elems + 255) / 256, 256>>>(Wo, bo, Wp, W1, b1);
    mlp_kernel<<<1024, 256>>>(W2, b2, W3, b3, W4, b4);
    gemm1_kernel<<<dim3(128, 8), 256>>>();
    gemm2_fused9<<<1024, 256, SM_TOT>>>(main_in, bp, out);
}